// round 1
// baseline (speedup 1.0000x reference)
#include <cuda_runtime.h>
#include <cstdint>

// ---------------- problem-size constants (dataset: N=100000, E=1600000, D=64) ----
#define MAXN 100000
#define DD   64
#define DD2  128

// ---------------- scratch (static __device__ globals; no allocation) -------------
__device__ float g_agg[(size_t)MAXN * DD];     // 25.6 MB  segment sums
__device__ float g_deg[MAXN];                  // degrees (float)
__device__ float g_t1[(size_t)MAXN * DD2];     // 51.2 MB  pre-BN GEMM1 output
__device__ float g_sum1[DD2], g_sumsq1[DD2], g_scale1[DD2], g_shift1[DD2];
__device__ float g_sum2[DD],  g_sumsq2[DD],  g_scale2[DD],  g_shift2[DD];

// ---------------- f32x2 helpers ---------------------------------------------------
__device__ __forceinline__ unsigned long long pack2(float lo, float hi) {
    unsigned long long r;
    asm("mov.b64 %0, {%1,%2};" : "=l"(r) : "f"(lo), "f"(hi));
    return r;
}
__device__ __forceinline__ void unpack2(unsigned long long v, float& lo, float& hi) {
    asm("mov.b64 {%0,%1}, %2;" : "=f"(lo), "=f"(hi) : "l"(v));
}
#define FMA2(acc, a, b) asm("fma.rn.f32x2 %0, %1, %2, %0;" : "+l"(acc) : "l"(a), "l"(b))

// ---------------- kernel 0: zero scratch ------------------------------------------
__global__ void zero_kernel(int n) {
    int stride = gridDim.x * blockDim.x;
    int i = blockIdx.x * blockDim.x + threadIdx.x;
    int total = n * DD;
    for (int idx = i; idx < total; idx += stride) g_agg[idx] = 0.0f;
    for (int idx = i; idx < n; idx += stride)     g_deg[idx] = 0.0f;
    if (i < DD2) { g_sum1[i] = 0.0f; g_sumsq1[i] = 0.0f; }
    if (i < DD)  { g_sum2[i] = 0.0f; g_sumsq2[i] = 0.0f; }
}

// ---------------- kernel 1: edge gather + scatter (16 threads / edge, float4) -----
__global__ void __launch_bounds__(256) edge_kernel(
    const float4* __restrict__ nf, const float4* __restrict__ ef,
    const int* __restrict__ src, const int* __restrict__ dst, int E)
{
    int t = blockIdx.x * blockDim.x + threadIdx.x;
    int e = t >> 4;
    int q = t & 15;
    if (e >= E) return;
    int s = __ldg(src + e);
    int d = __ldg(dst + e);
    float4 a = nf[(size_t)s * 16 + q];
    float4 b = ef[(size_t)e * 16 + q];
    float4 v = make_float4(a.x + b.x, a.y + b.y, a.z + b.z, a.w + b.w);
    atomicAdd(reinterpret_cast<float4*>(g_agg) + (size_t)d * 16 + q, v);
    if (q == 0) atomicAdd(&g_deg[d], 1.0f);
}

// ---------------- kernel 2: combine + GEMM1 (NxD @ DxD2) + column stats -----------
// block = 256 threads, tile = 128 rows x 128 cols, per-thread 8x8 via f32x2
#define HS_STRIDE 68   // 64 K-cols + pad; (68*4)%16==0 -> float4-aligned rows
__global__ void __launch_bounds__(256) gemm1_kernel(
    const float* __restrict__ nf, const float* __restrict__ eps,
    const float* __restrict__ W1, const float* __restrict__ b1, int N)
{
    extern __shared__ float sm[];
    float* hs = sm;                       // [128][HS_STRIDE]
    float* ws = sm + 128 * HS_STRIDE;     // [64][128]
    __shared__ float s_sum[DD2], s_sumsq[DD2];

    int tid = threadIdx.x;
    int r0  = blockIdx.x * 128;
    if (tid < DD2) { s_sum[tid] = 0.0f; s_sumsq[tid] = 0.0f; }
    float epsv = 1.0f + eps[0];

    // load W1 (64x128, contiguous)
    for (int idx = tid; idx < (64 * 128) / 4; idx += 256)
        reinterpret_cast<float4*>(ws)[idx] = reinterpret_cast<const float4*>(W1)[idx];

    // build h = (1+eps)*node + agg/max(deg,1) into smem (row-major, padded)
    for (int c = tid; c < 128 * 16; c += 256) {
        int row = c >> 4;
        int kc  = (c & 15) << 2;
        int rg  = r0 + row;
        float4 v = make_float4(0.f, 0.f, 0.f, 0.f);
        if (rg < N) {
            float4 a = *reinterpret_cast<const float4*>(nf + (size_t)rg * DD + kc);
            float4 g = *reinterpret_cast<const float4*>(g_agg + (size_t)rg * DD + kc);
            float rd = 1.0f / fmaxf(g_deg[rg], 1.0f);
            v.x = epsv * a.x + g.x * rd;
            v.y = epsv * a.y + g.y * rd;
            v.z = epsv * a.z + g.z * rd;
            v.w = epsv * a.w + g.w * rd;
        }
        *reinterpret_cast<float4*>(hs + row * HS_STRIDE + kc) = v;
    }
    __syncthreads();

    int tc = tid & 15;   // col group: cols tc*8 .. tc*8+7
    int tr = tid >> 4;   // row group: rows tr*8 .. tr*8+7

    unsigned long long acc[8][4];
#pragma unroll
    for (int i = 0; i < 8; i++)
#pragma unroll
        for (int j = 0; j < 4; j++) acc[i][j] = 0ull;

    const float* wp = ws + tc * 8;
    const float* hp = hs + (tr * 8) * HS_STRIDE;

#pragma unroll 4
    for (int k = 0; k < 64; k++) {
        float4 wA = *reinterpret_cast<const float4*>(wp + k * 128);
        float4 wB = *reinterpret_cast<const float4*>(wp + k * 128 + 4);
        unsigned long long w0 = pack2(wA.x, wA.y);
        unsigned long long w1 = pack2(wA.z, wA.w);
        unsigned long long w2 = pack2(wB.x, wB.y);
        unsigned long long w3 = pack2(wB.z, wB.w);
#pragma unroll
        for (int i = 0; i < 8; i++) {
            float hv = hp[i * HS_STRIDE + k];
            unsigned long long hh = pack2(hv, hv);
            FMA2(acc[i][0], hh, w0);
            FMA2(acc[i][1], hh, w1);
            FMA2(acc[i][2], hh, w2);
            FMA2(acc[i][3], hh, w3);
        }
    }

    // epilogue: +bias, store pre-BN z to g_t1, accumulate column stats
    float bb[8];
#pragma unroll
    for (int j = 0; j < 8; j++) bb[j] = __ldg(b1 + tc * 8 + j);
    float csum[8], csq[8];
#pragma unroll
    for (int j = 0; j < 8; j++) { csum[j] = 0.f; csq[j] = 0.f; }

#pragma unroll
    for (int i = 0; i < 8; i++) {
        int rg = r0 + tr * 8 + i;
        if (rg >= N) break;
        float z[8];
#pragma unroll
        for (int j = 0; j < 4; j++) unpack2(acc[i][j], z[2 * j], z[2 * j + 1]);
#pragma unroll
        for (int j = 0; j < 8; j++) z[j] += bb[j];
        float4* o = reinterpret_cast<float4*>(g_t1 + (size_t)rg * DD2 + tc * 8);
        o[0] = make_float4(z[0], z[1], z[2], z[3]);
        o[1] = make_float4(z[4], z[5], z[6], z[7]);
#pragma unroll
        for (int j = 0; j < 8; j++) { csum[j] += z[j]; csq[j] += z[j] * z[j]; }
    }
#pragma unroll
    for (int j = 0; j < 8; j++) {
        atomicAdd(&s_sum[tc * 8 + j], csum[j]);
        atomicAdd(&s_sumsq[tc * 8 + j], csq[j]);
    }
    __syncthreads();
    if (tid < DD2) {
        atomicAdd(&g_sum1[tid], s_sum[tid]);
        atomicAdd(&g_sumsq1[tid], s_sumsq[tid]);
    }
}

// ---------------- kernel 3: BN1 finalize ------------------------------------------
__global__ void finalize1_kernel(const float* __restrict__ gamma,
                                 const float* __restrict__ beta, float invN) {
    int i = threadIdx.x;  // 128
    float m = g_sum1[i] * invN;
    float v = fmaxf(g_sumsq1[i] * invN - m * m, 0.0f);
    float sc = gamma[i] * rsqrtf(v + 1e-5f);
    g_scale1[i] = sc;
    g_shift1[i] = beta[i] - m * sc;
}

// ---------------- kernel 4: BN1+ReLU + GEMM2 (NxD2 @ D2xD) + column stats ---------
#define XS_STRIDE 132  // 128 + pad; (132*4)%16==0
__global__ void __launch_bounds__(256) gemm2_kernel(
    const float* __restrict__ W2, const float* __restrict__ b2,
    float* __restrict__ out, int N)
{
    extern __shared__ float sm[];
    float* xs = sm;                        // [128][XS_STRIDE]
    float* ws = sm + 128 * XS_STRIDE;      // [128][64]
    __shared__ float s_sum[DD], s_sumsq[DD];

    int tid = threadIdx.x;
    int r0  = blockIdx.x * 128;
    if (tid < DD) { s_sum[tid] = 0.0f; s_sumsq[tid] = 0.0f; }

    // load W2 (128x64, contiguous)
    for (int idx = tid; idx < (128 * 64) / 4; idx += 256)
        reinterpret_cast<float4*>(ws)[idx] = reinterpret_cast<const float4*>(W2)[idx];

    // load x = relu(BN1(z1))
    for (int c = tid; c < 128 * 32; c += 256) {
        int row = c >> 5;
        int kc  = (c & 31) << 2;
        int rg  = r0 + row;
        float4 v = make_float4(0.f, 0.f, 0.f, 0.f);
        if (rg < N) {
            float4 z = *reinterpret_cast<const float4*>(g_t1 + (size_t)rg * DD2 + kc);
            v.x = fmaxf(fmaf(z.x, g_scale1[kc + 0], g_shift1[kc + 0]), 0.f);
            v.y = fmaxf(fmaf(z.y, g_scale1[kc + 1], g_shift1[kc + 1]), 0.f);
            v.z = fmaxf(fmaf(z.z, g_scale1[kc + 2], g_shift1[kc + 2]), 0.f);
            v.w = fmaxf(fmaf(z.w, g_scale1[kc + 3], g_shift1[kc + 3]), 0.f);
        }
        *reinterpret_cast<float4*>(xs + row * XS_STRIDE + kc) = v;
    }
    __syncthreads();

    int tc = tid & 15;   // cols tc*4 .. tc*4+3
    int tr = tid >> 4;   // rows tr*8 .. tr*8+7

    unsigned long long acc[8][2];
#pragma unroll
    for (int i = 0; i < 8; i++) { acc[i][0] = 0ull; acc[i][1] = 0ull; }

    const float* wp = ws + tc * 4;
    const float* hp = xs + (tr * 8) * XS_STRIDE;

#pragma unroll 4
    for (int k = 0; k < 128; k++) {
        float4 wA = *reinterpret_cast<const float4*>(wp + k * 64);
        unsigned long long w0 = pack2(wA.x, wA.y);
        unsigned long long w1 = pack2(wA.z, wA.w);
#pragma unroll
        for (int i = 0; i < 8; i++) {
            float hv = hp[i * XS_STRIDE + k];
            unsigned long long hh = pack2(hv, hv);
            FMA2(acc[i][0], hh, w0);
            FMA2(acc[i][1], hh, w1);
        }
    }

    float bb[4];
#pragma unroll
    for (int j = 0; j < 4; j++) bb[j] = __ldg(b2 + tc * 4 + j);
    float csum[4], csq[4];
#pragma unroll
    for (int j = 0; j < 4; j++) { csum[j] = 0.f; csq[j] = 0.f; }

#pragma unroll
    for (int i = 0; i < 8; i++) {
        int rg = r0 + tr * 8 + i;
        if (rg >= N) break;
        float z[4];
        unpack2(acc[i][0], z[0], z[1]);
        unpack2(acc[i][1], z[2], z[3]);
#pragma unroll
        for (int j = 0; j < 4; j++) z[j] += bb[j];
        *reinterpret_cast<float4*>(out + (size_t)rg * DD + tc * 4) =
            make_float4(z[0], z[1], z[2], z[3]);
#pragma unroll
        for (int j = 0; j < 4; j++) { csum[j] += z[j]; csq[j] += z[j] * z[j]; }
    }
#pragma unroll
    for (int j = 0; j < 4; j++) {
        atomicAdd(&s_sum[tc * 4 + j], csum[j]);
        atomicAdd(&s_sumsq[tc * 4 + j], csq[j]);
    }
    __syncthreads();
    if (tid < DD) {
        atomicAdd(&g_sum2[tid], s_sum[tid]);
        atomicAdd(&g_sumsq2[tid], s_sumsq[tid]);
    }
}

// ---------------- kernel 5: BN2 finalize ------------------------------------------
__global__ void finalize2_kernel(const float* __restrict__ gamma,
                                 const float* __restrict__ beta, float invN) {
    int i = threadIdx.x;  // 64
    float m = g_sum2[i] * invN;
    float v = fmaxf(g_sumsq2[i] * invN - m * m, 0.0f);
    float sc = gamma[i] * rsqrtf(v + 1e-5f);
    g_scale2[i] = sc;
    g_shift2[i] = beta[i] - m * sc;
}

// ---------------- kernel 6: BN2 + ReLU in place on d_out --------------------------
__global__ void bn2_kernel(float* __restrict__ out, int N) {
    int idx = blockIdx.x * blockDim.x + threadIdx.x;
    int total = N * 16;  // float4 chunks
    if (idx >= total) return;
    int c = (idx & 15) << 2;
    float4 z = reinterpret_cast<float4*>(out)[idx];
    z.x = fmaxf(fmaf(z.x, g_scale2[c + 0], g_shift2[c + 0]), 0.f);
    z.y = fmaxf(fmaf(z.y, g_scale2[c + 1], g_shift2[c + 1]), 0.f);
    z.z = fmaxf(fmaf(z.z, g_scale2[c + 2], g_shift2[c + 2]), 0.f);
    z.w = fmaxf(fmaf(z.w, g_scale2[c + 3], g_shift2[c + 3]), 0.f);
    reinterpret_cast<float4*>(out)[idx] = z;
}

// ---------------- launch -----------------------------------------------------------
extern "C" void kernel_launch(void* const* d_in, const int* in_sizes, int n_in,
                              void* d_out, int out_size) {
    const float* node_feats = (const float*)d_in[0];
    const float* edge_feats = (const float*)d_in[1];
    const int*   src        = (const int*)d_in[2];
    const int*   dst        = (const int*)d_in[3];
    const float* eps        = (const float*)d_in[4];
    const float* W1         = (const float*)d_in[5];
    const float* b1         = (const float*)d_in[6];
    const float* gamma1     = (const float*)d_in[7];
    const float* beta1      = (const float*)d_in[8];
    const float* W2         = (const float*)d_in[9];
    const float* b2         = (const float*)d_in[10];
    const float* gamma2     = (const float*)d_in[11];
    const float* beta2      = (const float*)d_in[12];
    float* out = (float*)d_out;

    int N = in_sizes[0] / DD;
    int E = in_sizes[1] / DD;

    // opt-in smem (>48KB) — idempotent, safe to call every launch
    size_t sm1 = (size_t)(128 * HS_STRIDE + 64 * 128) * sizeof(float);   // ~66 KB
    size_t sm2 = (size_t)(128 * XS_STRIDE + 128 * 64) * sizeof(float);   // ~98 KB
    cudaFuncSetAttribute(gemm1_kernel, cudaFuncAttributeMaxDynamicSharedMemorySize, (int)sm1);
    cudaFuncSetAttribute(gemm2_kernel, cudaFuncAttributeMaxDynamicSharedMemorySize, (int)sm2);

    zero_kernel<<<4096, 256>>>(N);
    edge_kernel<<<(E * 16 + 255) / 256, 256>>>(
        (const float4*)node_feats, (const float4*)edge_feats, src, dst, E);

    int nblk = (N + 127) / 128;
    gemm1_kernel<<<nblk, 256, sm1>>>(node_feats, eps, W1, b1, N);
    finalize1_kernel<<<1, DD2>>>(gamma1, beta1, 1.0f / (float)N);
    gemm2_kernel<<<nblk, 256, sm2>>>(W2, b2, out, N);
    finalize2_kernel<<<1, DD>>>(gamma2, beta2, 1.0f / (float)N);
    bn2_kernel<<<(N * 16 + 255) / 256, 256>>>(out, N);
}

// round 2
// speedup vs baseline: 1.0634x; 1.0634x over previous
#include <cuda_runtime.h>
#include <cstdint>

// ---------------- problem-size constants (dataset: N=100000, E=1600000, D=64) ----
#define MAXN 100000
#define DD   64
#define DD2  128

// ---------------- scratch (static __device__ globals; no allocation) -------------
__device__ float g_agg[(size_t)MAXN * DD];     // 25.6 MB  segment sums
__device__ float g_deg[MAXN];                  // degrees (float)
__device__ float g_t1[(size_t)MAXN * DD2];     // 51.2 MB  pre-BN GEMM1 output
__device__ float g_sum1[DD2], g_sumsq1[DD2];
__device__ float g_sum2[DD],  g_sumsq2[DD];

// ---------------- f32x2 helpers ---------------------------------------------------
__device__ __forceinline__ unsigned long long pack2(float lo, float hi) {
    unsigned long long r;
    asm("mov.b64 %0, {%1,%2};" : "=l"(r) : "f"(lo), "f"(hi));
    return r;
}
__device__ __forceinline__ void unpack2(unsigned long long v, float& lo, float& hi) {
    asm("mov.b64 {%0,%1}, %2;" : "=f"(lo), "=f"(hi) : "l"(v));
}
#define FMA2(acc, a, b) asm("fma.rn.f32x2 %0, %1, %2, %0;" : "+l"(acc) : "l"(a), "l"(b))

// ---------------- kernel 0: zero scratch ------------------------------------------
__global__ void zero_kernel(int n) {
    int stride = gridDim.x * blockDim.x;
    int i = blockIdx.x * blockDim.x + threadIdx.x;
    int total = n * DD;
    for (int idx = i; idx < total; idx += stride) g_agg[idx] = 0.0f;
    for (int idx = i; idx < n; idx += stride)     g_deg[idx] = 0.0f;
    if (i < DD2) { g_sum1[i] = 0.0f; g_sumsq1[i] = 0.0f; }
    if (i < DD)  { g_sum2[i] = 0.0f; g_sumsq2[i] = 0.0f; }
}

// ---------------- kernel 1: edge gather + scatter (16 threads / edge, float4) -----
// edge_feats is a 409.6MB one-shot stream: load with .cs (evict-first) so it does
// not thrash the L2-resident node_feats (25.6MB) gather set + atomic dest lines.
__global__ void __launch_bounds__(256) edge_kernel(
    const float4* __restrict__ nf, const float4* __restrict__ ef,
    const int* __restrict__ src, const int* __restrict__ dst, int E)
{
    int t = blockIdx.x * blockDim.x + threadIdx.x;
    int e = t >> 4;
    int q = t & 15;
    if (e >= E) return;
    int s = __ldg(src + e);
    int d = __ldg(dst + e);
    float4 a = __ldg(nf + (size_t)s * 16 + q);
    float4 b = __ldcs(ef + (size_t)e * 16 + q);
    float4 v = make_float4(a.x + b.x, a.y + b.y, a.z + b.z, a.w + b.w);
    atomicAdd(reinterpret_cast<float4*>(g_agg) + (size_t)d * 16 + q, v);
    if (q == 0) atomicAdd(&g_deg[d], 1.0f);
}

// ---------------- kernel 2: combine + GEMM1 (NxD @ DxD2) + column stats -----------
// block = 256 threads, tile = 128 rows x 128 cols, per-thread 8x8 via f32x2
#define HS_STRIDE 68   // 64 K-cols + pad; (68*4)%16==0 -> float4-aligned rows
__global__ void __launch_bounds__(256) gemm1_kernel(
    const float* __restrict__ nf, const float* __restrict__ eps,
    const float* __restrict__ W1, const float* __restrict__ b1, int N)
{
    extern __shared__ float sm[];
    float* hs = sm;                       // [128][HS_STRIDE]
    float* ws = sm + 128 * HS_STRIDE;     // [64][128]
    __shared__ float s_sum[DD2], s_sumsq[DD2];

    int tid = threadIdx.x;
    int r0  = blockIdx.x * 128;
    if (tid < DD2) { s_sum[tid] = 0.0f; s_sumsq[tid] = 0.0f; }
    float epsv = 1.0f + eps[0];

    // load W1 (64x128, contiguous)
    for (int idx = tid; idx < (64 * 128) / 4; idx += 256)
        reinterpret_cast<float4*>(ws)[idx] = reinterpret_cast<const float4*>(W1)[idx];

    // build h = (1+eps)*node + agg/max(deg,1) into smem (row-major, padded)
    for (int c = tid; c < 128 * 16; c += 256) {
        int row = c >> 4;
        int kc  = (c & 15) << 2;
        int rg  = r0 + row;
        float4 v = make_float4(0.f, 0.f, 0.f, 0.f);
        if (rg < N) {
            float4 a = *reinterpret_cast<const float4*>(nf + (size_t)rg * DD + kc);
            float4 g = *reinterpret_cast<const float4*>(g_agg + (size_t)rg * DD + kc);
            float rd = 1.0f / fmaxf(g_deg[rg], 1.0f);
            v.x = epsv * a.x + g.x * rd;
            v.y = epsv * a.y + g.y * rd;
            v.z = epsv * a.z + g.z * rd;
            v.w = epsv * a.w + g.w * rd;
        }
        *reinterpret_cast<float4*>(hs + row * HS_STRIDE + kc) = v;
    }
    __syncthreads();

    int tc = tid & 15;   // col group: cols tc*8 .. tc*8+7
    int tr = tid >> 4;   // row group: rows tr*8 .. tr*8+7

    unsigned long long acc[8][4];
#pragma unroll
    for (int i = 0; i < 8; i++)
#pragma unroll
        for (int j = 0; j < 4; j++) acc[i][j] = 0ull;

    const float* wp = ws + tc * 8;
    const float* hp = hs + (tr * 8) * HS_STRIDE;

#pragma unroll 4
    for (int k = 0; k < 64; k++) {
        // wp row is 32B-aligned: reinterpret directly as packed f32x2 pairs
        ulonglong2 wA = *reinterpret_cast<const ulonglong2*>(wp + k * 128);
        ulonglong2 wB = *reinterpret_cast<const ulonglong2*>(wp + k * 128 + 4);
#pragma unroll
        for (int i = 0; i < 8; i++) {
            float hv = hp[i * HS_STRIDE + k];
            unsigned long long hh = pack2(hv, hv);
            FMA2(acc[i][0], hh, wA.x);
            FMA2(acc[i][1], hh, wA.y);
            FMA2(acc[i][2], hh, wB.x);
            FMA2(acc[i][3], hh, wB.y);
        }
    }

    // epilogue: +bias, store pre-BN z to g_t1, accumulate column stats
    float bb[8];
#pragma unroll
    for (int j = 0; j < 8; j++) bb[j] = __ldg(b1 + tc * 8 + j);
    float csum[8], csq[8];
#pragma unroll
    for (int j = 0; j < 8; j++) { csum[j] = 0.f; csq[j] = 0.f; }

#pragma unroll
    for (int i = 0; i < 8; i++) {
        int rg = r0 + tr * 8 + i;
        if (rg >= N) break;
        float z[8];
#pragma unroll
        for (int j = 0; j < 4; j++) unpack2(acc[i][j], z[2 * j], z[2 * j + 1]);
#pragma unroll
        for (int j = 0; j < 8; j++) z[j] += bb[j];
        float4* o = reinterpret_cast<float4*>(g_t1 + (size_t)rg * DD2 + tc * 8);
        o[0] = make_float4(z[0], z[1], z[2], z[3]);
        o[1] = make_float4(z[4], z[5], z[6], z[7]);
#pragma unroll
        for (int j = 0; j < 8; j++) { csum[j] += z[j]; csq[j] += z[j] * z[j]; }
    }
#pragma unroll
    for (int j = 0; j < 8; j++) {
        atomicAdd(&s_sum[tc * 8 + j], csum[j]);
        atomicAdd(&s_sumsq[tc * 8 + j], csq[j]);
    }
    __syncthreads();
    if (tid < DD2) {
        atomicAdd(&g_sum1[tid], s_sum[tid]);
        atomicAdd(&g_sumsq1[tid], s_sumsq[tid]);
    }
}

// ---------------- kernel 3: BN1(inline)+ReLU + GEMM2 (NxD2 @ D2xD) + stats --------
#define XS_STRIDE 132  // 128 + pad; (132*4)%16==0
__global__ void __launch_bounds__(256) gemm2_kernel(
    const float* __restrict__ W2, const float* __restrict__ b2,
    const float* __restrict__ gamma1, const float* __restrict__ beta1,
    float* __restrict__ out, int N, float invN)
{
    extern __shared__ float sm[];
    float* xs = sm;                        // [128][XS_STRIDE]
    float* ws = sm + 128 * XS_STRIDE;      // [128][64]
    __shared__ float s_sum[DD], s_sumsq[DD];
    __shared__ float s_scale1[DD2], s_shift1[DD2];

    int tid = threadIdx.x;
    int r0  = blockIdx.x * 128;
    if (tid < DD) { s_sum[tid] = 0.0f; s_sumsq[tid] = 0.0f; }

    // BN1 finalize (folded, per-block redundant — 128 rsqrt, trivial)
    if (tid < DD2) {
        float m = g_sum1[tid] * invN;
        float v = fmaxf(g_sumsq1[tid] * invN - m * m, 0.0f);
        float sc = __ldg(gamma1 + tid) * rsqrtf(v + 1e-5f);
        s_scale1[tid] = sc;
        s_shift1[tid] = __ldg(beta1 + tid) - m * sc;
    }

    // load W2 (128x64, contiguous)
    for (int idx = tid; idx < (128 * 64) / 4; idx += 256)
        reinterpret_cast<float4*>(ws)[idx] = reinterpret_cast<const float4*>(W2)[idx];
    __syncthreads();   // s_scale1/s_shift1 ready

    // load x = relu(BN1(z1))
    for (int c = tid; c < 128 * 32; c += 256) {
        int row = c >> 5;
        int kc  = (c & 31) << 2;
        int rg  = r0 + row;
        float4 v = make_float4(0.f, 0.f, 0.f, 0.f);
        if (rg < N) {
            float4 z = *reinterpret_cast<const float4*>(g_t1 + (size_t)rg * DD2 + kc);
            v.x = fmaxf(fmaf(z.x, s_scale1[kc + 0], s_shift1[kc + 0]), 0.f);
            v.y = fmaxf(fmaf(z.y, s_scale1[kc + 1], s_shift1[kc + 1]), 0.f);
            v.z = fmaxf(fmaf(z.z, s_scale1[kc + 2], s_shift1[kc + 2]), 0.f);
            v.w = fmaxf(fmaf(z.w, s_scale1[kc + 3], s_shift1[kc + 3]), 0.f);
        }
        *reinterpret_cast<float4*>(xs + row * XS_STRIDE + kc) = v;
    }
    __syncthreads();

    int tc = tid & 15;   // cols tc*4 .. tc*4+3
    int tr = tid >> 4;   // rows tr*8 .. tr*8+7

    unsigned long long acc[8][2];
#pragma unroll
    for (int i = 0; i < 8; i++) { acc[i][0] = 0ull; acc[i][1] = 0ull; }

    const float* wp = ws + tc * 4;
    const float* hp = xs + (tr * 8) * XS_STRIDE;

#pragma unroll 4
    for (int k = 0; k < 128; k++) {
        ulonglong2 wA = *reinterpret_cast<const ulonglong2*>(wp + k * 64);
#pragma unroll
        for (int i = 0; i < 8; i++) {
            float hv = hp[i * XS_STRIDE + k];
            unsigned long long hh = pack2(hv, hv);
            FMA2(acc[i][0], hh, wA.x);
            FMA2(acc[i][1], hh, wA.y);
        }
    }

    float bb[4];
#pragma unroll
    for (int j = 0; j < 4; j++) bb[j] = __ldg(b2 + tc * 4 + j);
    float csum[4], csq[4];
#pragma unroll
    for (int j = 0; j < 4; j++) { csum[j] = 0.f; csq[j] = 0.f; }

#pragma unroll
    for (int i = 0; i < 8; i++) {
        int rg = r0 + tr * 8 + i;
        if (rg >= N) break;
        float z[4];
        unpack2(acc[i][0], z[0], z[1]);
        unpack2(acc[i][1], z[2], z[3]);
#pragma unroll
        for (int j = 0; j < 4; j++) z[j] += bb[j];
        *reinterpret_cast<float4*>(out + (size_t)rg * DD + tc * 4) =
            make_float4(z[0], z[1], z[2], z[3]);
#pragma unroll
        for (int j = 0; j < 4; j++) { csum[j] += z[j]; csq[j] += z[j] * z[j]; }
    }
#pragma unroll
    for (int j = 0; j < 4; j++) {
        atomicAdd(&s_sum[tc * 4 + j], csum[j]);
        atomicAdd(&s_sumsq[tc * 4 + j], csq[j]);
    }
    __syncthreads();
    if (tid < DD) {
        atomicAdd(&g_sum2[tid], s_sum[tid]);
        atomicAdd(&g_sumsq2[tid], s_sumsq[tid]);
    }
}

// ---------------- kernel 4: BN2 finalize (folded) + BN2 + ReLU in place -----------
__global__ void __launch_bounds__(256) bn2_kernel(
    float* __restrict__ out, const float* __restrict__ gamma2,
    const float* __restrict__ beta2, int N, float invN)
{
    __shared__ float s_scale2[DD], s_shift2[DD];
    int tid = threadIdx.x;
    if (tid < DD) {
        float m = g_sum2[tid] * invN;
        float v = fmaxf(g_sumsq2[tid] * invN - m * m, 0.0f);
        float sc = __ldg(gamma2 + tid) * rsqrtf(v + 1e-5f);
        s_scale2[tid] = sc;
        s_shift2[tid] = __ldg(beta2 + tid) - m * sc;
    }
    __syncthreads();

    int idx = blockIdx.x * blockDim.x + tid;
    int total = N * 16;  // float4 chunks
    if (idx >= total) return;
    int c = (idx & 15) << 2;
    float4 z = reinterpret_cast<float4*>(out)[idx];
    z.x = fmaxf(fmaf(z.x, s_scale2[c + 0], s_shift2[c + 0]), 0.f);
    z.y = fmaxf(fmaf(z.y, s_scale2[c + 1], s_shift2[c + 1]), 0.f);
    z.z = fmaxf(fmaf(z.z, s_scale2[c + 2], s_shift2[c + 2]), 0.f);
    z.w = fmaxf(fmaf(z.w, s_scale2[c + 3], s_shift2[c + 3]), 0.f);
    reinterpret_cast<float4*>(out)[idx] = z;
}

// ---------------- launch -----------------------------------------------------------
extern "C" void kernel_launch(void* const* d_in, const int* in_sizes, int n_in,
                              void* d_out, int out_size) {
    const float* node_feats = (const float*)d_in[0];
    const float* edge_feats = (const float*)d_in[1];
    const int*   src        = (const int*)d_in[2];
    const int*   dst        = (const int*)d_in[3];
    const float* eps        = (const float*)d_in[4];
    const float* W1         = (const float*)d_in[5];
    const float* b1         = (const float*)d_in[6];
    const float* gamma1     = (const float*)d_in[7];
    const float* beta1      = (const float*)d_in[8];
    const float* W2         = (const float*)d_in[9];
    const float* b2         = (const float*)d_in[10];
    const float* gamma2     = (const float*)d_in[11];
    const float* beta2      = (const float*)d_in[12];
    float* out = (float*)d_out;

    int N = in_sizes[0] / DD;
    int E = in_sizes[1] / DD;
    float invN = 1.0f / (float)N;

    // opt-in smem (>48KB) — idempotent, safe to call every launch
    size_t sm1 = (size_t)(128 * HS_STRIDE + 64 * 128) * sizeof(float);   // ~66 KB
    size_t sm2 = (size_t)(128 * XS_STRIDE + 128 * 64) * sizeof(float);   // ~98 KB
    cudaFuncSetAttribute(gemm1_kernel, cudaFuncAttributeMaxDynamicSharedMemorySize, (int)sm1);
    cudaFuncSetAttribute(gemm2_kernel, cudaFuncAttributeMaxDynamicSharedMemorySize, (int)sm2);

    zero_kernel<<<4096, 256>>>(N);
    edge_kernel<<<(E * 16 + 255) / 256, 256>>>(
        (const float4*)node_feats, (const float4*)edge_feats, src, dst, E);

    int nblk = (N + 127) / 128;
    gemm1_kernel<<<nblk, 256, sm1>>>(node_feats, eps, W1, b1, N);
    gemm2_kernel<<<nblk, 256, sm2>>>(W2, b2, gamma1, beta1, out, N, invN);
    bn2_kernel<<<(N * 16 + 255) / 256, 256>>>(out, gamma2, beta2, N, invN);
}